// round 14
// baseline (speedup 1.0000x reference)
#include <cuda_runtime.h>
#include <cuda_fp16.h>
#include <cstdint>

#define BATCHN 4
#define SEQL   2048
#define EMB    1024
#define NHEAD  16
#define DKH    64
#define MROWS  (BATCHN*SEQL)   /* 8192 */
#define BH     (BATCHN*NHEAD)  /* 64 */

// ---------------- scratch (static device globals; no runtime allocation) ----
__device__ unsigned g_xh[3][(size_t)MROWS*512];   // x hi, [row][kpair]
__device__ unsigned g_xl[3][(size_t)MROWS*512];   // lo
__device__ unsigned g_wh[4][(size_t)1024*512];    // weights hi, [col][kpair]  (BT layout)
__device__ unsigned g_wl[4][(size_t)1024*512];
__device__ unsigned g_qh[(size_t)BH*SEQL*32];     // q hi (scaled by 8*log2e)
__device__ unsigned g_ql[(size_t)BH*SEQL*32];
__device__ unsigned g_kh[(size_t)BH*SEQL*32];
__device__ unsigned g_kl[(size_t)BH*SEQL*32];
__device__ unsigned g_vh[(size_t)BH*SEQL*32];     // v hi only
__device__ unsigned g_ah[(size_t)MROWS*512];      // attn out hi, [row][epair]
__device__ unsigned g_al[(size_t)MROWS*512];

#define LOG2E 1.4426950408889634f

// ---------------- helpers ---------------------------------------------------
__device__ __forceinline__ void mma16h(float c[4], unsigned a0, unsigned a1, unsigned a2, unsigned a3,
                                       unsigned b0, unsigned b1) {
    asm volatile(
        "mma.sync.aligned.m16n8k16.row.col.f32.f16.f16.f32 "
        "{%0,%1,%2,%3},{%4,%5,%6,%7},{%8,%9},{%0,%1,%2,%3};\n"
        : "+f"(c[0]), "+f"(c[1]), "+f"(c[2]), "+f"(c[3])
        : "r"(a0), "r"(a1), "r"(a2), "r"(a3), "r"(b0), "r"(b1));
}
__device__ __forceinline__ void ldm4(uint4 &r, uint32_t a) {
    asm volatile("ldmatrix.sync.aligned.m8n8.x4.shared.b16 {%0,%1,%2,%3}, [%4];"
                 : "=r"(r.x), "=r"(r.y), "=r"(r.z), "=r"(r.w) : "r"(a));
}
__device__ __forceinline__ void split_h2(float x0, float x1, unsigned &hi, unsigned &lo) {
    __half2 H = __floats2half2_rn(x0, x1);
    float2 f = __half22float2(H);
    __half2 L = __floats2half2_rn(x0 - f.x, x1 - f.y);
    hi = *reinterpret_cast<unsigned*>(&H);
    lo = *reinterpret_cast<unsigned*>(&L);
}
__device__ __forceinline__ unsigned pack_h2(float x0, float x1) {
    __half2 H = __floats2half2_rn(x0, x1);
    return *reinterpret_cast<unsigned*>(&H);
}
__device__ __forceinline__ uint32_t smem_u32(const void* p) {
    uint32_t a;
    asm("{ .reg .u64 t; cvta.to.shared.u64 t, %1; cvt.u32.u64 %0, t; }" : "=r"(a) : "l"(p));
    return a;
}
#define CPA16(dst, src) asm volatile("cp.async.cg.shared.global [%0], [%1], 16;" :: "r"(dst), "l"(src))
#define CPA_COMMIT()    asm volatile("cp.async.commit_group;" ::: "memory")
#define CPA_WAIT0()     asm volatile("cp.async.wait_group 0;" ::: "memory")

// ---------------- conversion kernels -----------------------------------------
__global__ void __launch_bounds__(256) conv_x_kernel(
    const float* __restrict__ x0, const float* __restrict__ x1, const float* __restrict__ x2)
{
    int sel = blockIdx.z;
    const float* x = sel == 0 ? x0 : (sel == 1 ? x1 : x2);
    size_t idx = (size_t)blockIdx.x * 256 + threadIdx.x;
    float2 v = *reinterpret_cast<const float2*>(x + 2 * idx);
    unsigned h, l;
    split_h2(v.x, v.y, h, l);
    g_xh[sel][idx] = h;
    g_xl[sel][idx] = l;
}

// weights -> split packed, BT layout: g_w[col*512 + kpair]
__global__ void __launch_bounds__(256) conv_w_kernel(
    const float* __restrict__ w0, const float* __restrict__ w1,
    const float* __restrict__ w2, const float* __restrict__ w3)
{
    int wsel = blockIdx.y;
    const float* W = wsel == 0 ? w0 : (wsel == 1 ? w1 : (wsel == 2 ? w2 : w3));
    size_t idx = (size_t)blockIdx.x * 256 + threadIdx.x;   // < 512*1024
    int p   = (int)(idx >> 10);        // kpair
    int col = (int)(idx & 1023);       // output column (reads coalesced over col)
    float v0, v1;
    if (wsel < 3) {
        int head = col >> 6, d = col & 63;
        size_t base = (size_t)head * EMB * 64 + (size_t)(2 * p) * 64 + d;
        v0 = W[base];
        v1 = W[base + 64];
    } else {
        v0 = W[(size_t)(2 * p) * EMB + col];
        v1 = W[(size_t)(2 * p + 1) * EMB + col];
    }
    unsigned h, l;
    split_h2(v0, v1, h, l);
    g_wh[wsel][(size_t)col * 512 + p] = h;
    g_wl[wsel][(size_t)col * 512 + p] = l;
}

// ---------------- GEMM (pre-split fp16, ldmatrix fragments) ------------------
// A tile:  [128 rows][TW=20 kpair words] hi+lo.
// BT tile: [128 cols][TW=20 kpair words] hi(+lo x3).  Same layout as A.
#define TW 20
#define CHUNK 32

template<int MODE, int PASSES>
__global__ void __launch_bounds__(256, 2) gemm_p_kernel(float* __restrict__ Cext, int selbase)
{
    constexpr int G_AH = 0;
    constexpr int G_AL = 128 * TW;
    constexpr int G_BH = 2 * 128 * TW;
    constexpr int G_BL = 3 * 128 * TW;
    constexpr int GSTAGE = ((PASSES >= 3) ? 4 : 3) * 128 * TW;
    constexpr int NCH = EMB / CHUNK;   // 32
    constexpr int BKP = CHUNK / 2;     // 16

    extern __shared__ unsigned smu[];
    const uint32_t sbase = smem_u32(smu);

    const int tid  = threadIdx.x;
    const int lane = tid & 31;
    const int warp = tid >> 5;
    const int wm = warp >> 1, wn = warp & 1;
    const int row0 = blockIdx.x * 128;
    const int col0 = blockIdx.y * 128;

    int sel = (MODE == 0) ? (blockIdx.z + selbase) : 3;
    const unsigned* Ahg = (MODE == 0) ? g_xh[sel] : g_ah;
    const unsigned* Alg = (MODE == 0) ? g_xl[sel] : g_al;
    const unsigned* Whg = g_wh[sel];
    const unsigned* Wlg = g_wl[sel];

    float acc[2][8][4];
#pragma unroll
    for (int i = 0; i < 2; i++)
#pragma unroll
        for (int j = 0; j < 8; j++)
#pragma unroll
            for (int r = 0; r < 4; r++) acc[i][j][r] = 0.f;

    // producers
    const int am = tid & 127;          // A row
    const int ps = tid >> 7;           // A word part

    // ldmatrix per-lane base offsets (words)
    const int a_off = (wm * 32 + (lane & 15)) * TW + (lane >> 4) * 4;
    const int b_off = (wn * 64 + ((lane >> 4) << 3) + (lane & 7)) * TW + ((lane >> 3) & 1) * 4;

    auto issue = [&](int c, int st) {
        {   // A hi + lo
            const unsigned* srcH = Ahg + (size_t)(row0 + am) * 512 + c * BKP + ps * 8;
            const unsigned* srcL = Alg + (size_t)(row0 + am) * 512 + c * BKP + ps * 8;
            uint32_t dH = sbase + (uint32_t)(st * GSTAGE + G_AH + am * TW + ps * 8) * 4;
            uint32_t dL = sbase + (uint32_t)(st * GSTAGE + G_AL + am * TW + ps * 8) * 4;
            CPA16(dH, srcH); CPA16(dH + 16, srcH + 4);
            CPA16(dL, srcL); CPA16(dL + 16, srcL + 4);
        }
        {   // BT hi (+lo): 128 cols x 16 words; seg = col*4parts
#pragma unroll
            for (int a = 0; a < 2; a++) {
                int seg = tid + a * 256;
                int cl = seg >> 2, pt = (seg & 3) * 4;
                const unsigned* srcH = Whg + (size_t)(col0 + cl) * 512 + c * BKP + pt;
                uint32_t dH = sbase + (uint32_t)(st * GSTAGE + G_BH + cl * TW + pt) * 4;
                CPA16(dH, srcH);
                if (PASSES >= 3) {
                    const unsigned* srcL = Wlg + (size_t)(col0 + cl) * 512 + c * BKP + pt;
                    uint32_t dL = sbase + (uint32_t)(st * GSTAGE + G_BL + cl * TW + pt) * 4;
                    CPA16(dL, srcL);
                }
            }
        }
        CPA_COMMIT();
    };

    issue(0, 0);

    for (int c = 0; c < NCH; c++) {
        const int st = c & 1;
        CPA_WAIT0();
        __syncthreads();
        if (c + 1 < NCH) issue(c + 1, st ^ 1);

        const uint32_t stb = sbase + (uint32_t)(st * GSTAGE) * 4;

#pragma unroll
        for (int ks = 0; ks < 2; ks++) {
            const int kw = ks * 8;
            // A fragments via ldmatrix.x4 (hi + lo per mt)
            uint4 ah[2], al[2];
#pragma unroll
            for (int mt = 0; mt < 2; mt++) {
                uint32_t aw = stb + (uint32_t)(a_off + mt * 16 * TW + kw) * 4;
                ldm4(ah[mt], aw + G_AH * 4);
                ldm4(al[mt], aw + G_AL * 4);
            }
            // B fragments: 4 x4-ldmatrix cover nt pairs
#pragma unroll
            for (int ntp = 0; ntp < 4; ntp++) {
                uint32_t bw = stb + (uint32_t)(b_off + ntp * 16 * TW + kw) * 4;
                uint4 bh; ldm4(bh, bw + G_BH * 4);
#pragma unroll
                for (int mt = 0; mt < 2; mt++) {
                    mma16h(acc[mt][2*ntp],   ah[mt].x, ah[mt].y, ah[mt].z, ah[mt].w, bh.x, bh.y);
                    mma16h(acc[mt][2*ntp+1], ah[mt].x, ah[mt].y, ah[mt].z, ah[mt].w, bh.z, bh.w);
                    if (PASSES >= 2) {
                        mma16h(acc[mt][2*ntp],   al[mt].x, al[mt].y, al[mt].z, al[mt].w, bh.x, bh.y);
                        mma16h(acc[mt][2*ntp+1], al[mt].x, al[mt].y, al[mt].z, al[mt].w, bh.z, bh.w);
                    }
                }
                if (PASSES >= 3) {
                    uint4 bl; ldm4(bl, bw + G_BL * 4);
#pragma unroll
                    for (int mt = 0; mt < 2; mt++) {
                        mma16h(acc[mt][2*ntp],   ah[mt].x, ah[mt].y, ah[mt].z, ah[mt].w, bl.x, bl.y);
                        mma16h(acc[mt][2*ntp+1], ah[mt].x, ah[mt].y, ah[mt].z, ah[mt].w, bl.z, bl.w);
                    }
                }
            }
        }
        __syncthreads();
    }

    // ---- epilogue ----
    const float qscale = 8.f * LOG2E;
    const int r8 = lane >> 2, lq = lane & 3;
#pragma unroll
    for (int mt = 0; mt < 2; mt++) {
        int r = row0 + wm * 32 + mt * 16 + r8;
#pragma unroll
        for (int nt = 0; nt < 8; nt++) {
            int cc = wn * 64 + nt * 8 + lq * 2;
            if (MODE == 0) {
                int b = r >> 11, s = r & 2047;
                int head = blockIdx.y * 2 + (cc >> 6);
                int w = (cc & 63) >> 1;
                size_t widx  = ((size_t)(b * NHEAD + head) * SEQL + s) * 32 + w;
                size_t widx2 = widx + (size_t)8 * 32;
                float v0 = acc[mt][nt][0], v1 = acc[mt][nt][1];
                float v2 = acc[mt][nt][2], v3 = acc[mt][nt][3];
                if (sel == 0) { v0 *= qscale; v1 *= qscale; v2 *= qscale; v3 *= qscale; }
                unsigned h0, l0, h1, l1;
                split_h2(v0, v1, h0, l0);
                split_h2(v2, v3, h1, l1);
                if (sel == 0) {
                    g_qh[widx] = h0;  g_ql[widx] = l0;
                    g_qh[widx2] = h1; g_ql[widx2] = l1;
                } else if (sel == 1) {
                    g_kh[widx] = h0;  g_kl[widx] = l0;
                    g_kh[widx2] = h1; g_kl[widx2] = l1;
                } else {
                    g_vh[widx] = h0;
                    g_vh[widx2] = h1;
                }
            } else {
                size_t base = (size_t)r * EMB + col0 + cc;
                Cext[base]               = acc[mt][nt][0];
                Cext[base + 1]           = acc[mt][nt][1];
                Cext[base + 8 * EMB]     = acc[mt][nt][2];
                Cext[base + 8 * EMB + 1] = acc[mt][nt][3];
            }
        }
    }
}

#define GSM3_BYTES (2 * 4*128*TW * 4)   /* 81920 */
#define GSM2_BYTES (2 * 3*128*TW * 4)   /* 61440 */

// ---------------- flash attention (causal), pre-split fp16 — as R11 ----------
#define QW 36
#define KW 36
#define PW 68
#define FQ_H 0
#define FQ_L (128*QW)
#define FK_H 0
#define FK_L (64*KW)
#define FV_H (2*64*KW)
#define FSM_WORDS (2*128*QW)
#define FSM_BYTES (FSM_WORDS*4)

__global__ void __launch_bounds__(256) flash_kernel(const int* __restrict__ maskp)
{
    extern __shared__ unsigned smw[];

    const int tid  = threadIdx.x;
    const int lane = tid & 31;
    const int warp = tid >> 5;
    const int r8 = lane >> 2, lq = lane & 3;
    const int qt = blockIdx.x;
    const int bh = blockIdx.y;
    const int b = bh >> 4, h = bh & 15;
    const int q0 = qt * 128;
    const size_t sb = (size_t)bh * SEQL;

#pragma unroll
    for (int ii = 0; ii < 4; ii++) {
        int i = tid + ii * 256;
        int r = i >> 3, sg = (i & 7) * 4;
        uint4 vh = *reinterpret_cast<const uint4*>(g_qh + (sb + q0 + r) * 32 + sg);
        uint4 vl = *reinterpret_cast<const uint4*>(g_ql + (sb + q0 + r) * 32 + sg);
        *reinterpret_cast<uint4*>(smw + FQ_H + r * QW + sg) = vh;
        *reinterpret_cast<uint4*>(smw + FQ_L + r * QW + sg) = vl;
    }
    __syncthreads();

    const int rl = warp * 16 + r8;
    unsigned qh[4][4], ql[4][4];
#pragma unroll
    for (int ks = 0; ks < 4; ks++) {
        int base = rl * QW + ks * 8 + lq;
        qh[ks][0] = smw[FQ_H + base];
        qh[ks][1] = smw[FQ_H + base + 8 * QW];
        qh[ks][2] = smw[FQ_H + base + 4];
        qh[ks][3] = smw[FQ_H + base + 8 * QW + 4];
        ql[ks][0] = smw[FQ_L + base];
        ql[ks][1] = smw[FQ_L + base + 8 * QW];
        ql[ks][2] = smw[FQ_L + base + 4];
        ql[ks][3] = smw[FQ_L + base + 8 * QW + 4];
    }
    __syncthreads();

    float m[2] = { -1e30f, -1e30f };
    float l[2] = { 0.f, 0.f };
    float o[8][4];
#pragma unroll
    for (int i = 0; i < 8; i++)
#pragma unroll
        for (int j = 0; j < 4; j++) o[i][j] = 0.f;

    const int maskv = maskp[0];
    const int tdiag = 2 * qt + (warp >> 2);
    const int ntiles = maskv ? (2 * qt + 2) : (SEQL / 64);

    __half* vhp = reinterpret_cast<__half*>(smw + FV_H);

    for (int t = 0; t < ntiles; t++) {
        const int kv0 = t * 64;

        if (t > 0) __syncthreads();
#pragma unroll
        for (int ii = 0; ii < 2; ii++) {
            int i = tid + ii * 256;
            int r = i >> 3, sg = (i & 7) * 4;
            uint4 vh = *reinterpret_cast<const uint4*>(g_kh + (sb + kv0 + r) * 32 + sg);
            uint4 vl = *reinterpret_cast<const uint4*>(g_kl + (sb + kv0 + r) * 32 + sg);
            *reinterpret_cast<uint4*>(smw + FK_H + r * KW + sg) = vh;
            *reinterpret_cast<uint4*>(smw + FK_L + r * KW + sg) = vl;
        }
#pragma unroll
        for (int ii = 0; ii < 4; ii++) {
            int i = tid + ii * 256;
            int r = i >> 4, c4 = (i & 15) << 2;
            uint2 w2 = *reinterpret_cast<const uint2*>(g_vh + (sb + kv0 + r) * 32 + (c4 >> 1));
            __half2 p0 = *reinterpret_cast<__half2*>(&w2.x);
            __half2 p1 = *reinterpret_cast<__half2*>(&w2.y);
            int p = r >> 1, rb = r & 1;
            vhp[(p * PW + c4 + 0) * 2 + rb] = __low2half(p0);
            vhp[(p * PW + c4 + 1) * 2 + rb] = __high2half(p0);
            vhp[(p * PW + c4 + 2) * 2 + rb] = __low2half(p1);
            vhp[(p * PW + c4 + 3) * 2 + rb] = __high2half(p1);
        }
        __syncthreads();

        if (maskv && t > tdiag) continue;

        float s[8][4];
#pragma unroll
        for (int i = 0; i < 8; i++)
#pragma unroll
            for (int j = 0; j < 4; j++) s[i][j] = 0.f;

#pragma unroll
        for (int ks = 0; ks < 4; ks++) {
#pragma unroll
            for (int nt = 0; nt < 8; nt++) {
                int n = nt * 8 + r8;
                unsigned bh0 = smw[FK_H + n * KW + ks * 8 + lq];
                unsigned bh1 = smw[FK_H + n * KW + ks * 8 + lq + 4];
                unsigned bl0 = smw[FK_L + n * KW + ks * 8 + lq];
                unsigned bl1 = smw[FK_L + n * KW + ks * 8 + lq + 4];
                mma16h(s[nt], qh[ks][0], qh[ks][1], qh[ks][2], qh[ks][3], bh0, bh1);
                mma16h(s[nt], qh[ks][0], qh[ks][1], qh[ks][2], qh[ks][3], bl0, bl1);
                mma16h(s[nt], ql[ks][0], ql[ks][1], ql[ks][2], ql[ks][3], bh0, bh1);
            }
        }

        if (maskv && t == tdiag) {
            int rg0 = q0 + rl;
#pragma unroll
            for (int nt = 0; nt < 8; nt++) {
                int cg = kv0 + nt * 8 + lq * 2;
                if (cg > rg0)         s[nt][0] = -1e30f;
                if (cg + 1 > rg0)     s[nt][1] = -1e30f;
                if (cg > rg0 + 8)     s[nt][2] = -1e30f;
                if (cg + 1 > rg0 + 8) s[nt][3] = -1e30f;
            }
        }

#pragma unroll
        for (int sub = 0; sub < 2; sub++) {
            float tm = -1e30f;
#pragma unroll
            for (int nt = 0; nt < 8; nt++)
                tm = fmaxf(tm, fmaxf(s[nt][2 * sub], s[nt][2 * sub + 1]));
            tm = fmaxf(tm, __shfl_xor_sync(0xffffffffu, tm, 1));
            tm = fmaxf(tm, __shfl_xor_sync(0xffffffffu, tm, 2));
            float mn = fmaxf(m[sub], tm);
            float alpha = exp2f(m[sub] - mn);
            float rs = 0.f;
#pragma unroll
            for (int nt = 0; nt < 8; nt++) {
                float p0 = exp2f(s[nt][2 * sub] - mn);
                float p1 = exp2f(s[nt][2 * sub + 1] - mn);
                s[nt][2 * sub] = p0; s[nt][2 * sub + 1] = p1;
                rs += p0 + p1;
            }
            rs += __shfl_xor_sync(0xffffffffu, rs, 1);
            rs += __shfl_xor_sync(0xffffffffu, rs, 2);
            l[sub] = l[sub] * alpha + rs;
            m[sub] = mn;
#pragma unroll
            for (int dt = 0; dt < 8; dt++) {
                o[dt][2 * sub]     *= alpha;
                o[dt][2 * sub + 1] *= alpha;
            }
        }

        unsigned pa[4][4];
#pragma unroll
        for (int ks = 0; ks < 4; ks++) {
            pa[ks][0] = pack_h2(s[2*ks][0],   s[2*ks][1]);
            pa[ks][1] = pack_h2(s[2*ks][2],   s[2*ks][3]);
            pa[ks][2] = pack_h2(s[2*ks+1][0], s[2*ks+1][1]);
            pa[ks][3] = pack_h2(s[2*ks+1][2], s[2*ks+1][3]);
        }

        int ksmax = (maskv && t == tdiag) ? ((warp & 3) + 1) : 4;
#pragma unroll
        for (int ks = 0; ks < 4; ks++) {
            if (ks >= ksmax) break;
#pragma unroll
            for (int dt = 0; dt < 8; dt++) {
                int d = dt * 8 + r8;
                unsigned bh0 = smw[FV_H + (ks * 8 + lq) * PW + d];
                unsigned bh1 = smw[FV_H + (ks * 8 + lq + 4) * PW + d];
                mma16h(o[dt], pa[ks][0], pa[ks][1], pa[ks][2], pa[ks][3], bh0, bh1);
            }
        }
    }

    float i0 = 1.f / l[0];
    float i1 = 1.f / l[1];
    int rg = q0 + rl;
    size_t row  = (size_t)(b * SEQL + rg) * 512;
    size_t row2 = row + (size_t)8 * 512;
#pragma unroll
    for (int dt = 0; dt < 8; dt++) {
        int w = h * 32 + dt * 4 + lq;
        unsigned h0, l0, h1, l1;
        split_h2(o[dt][0] * i0, o[dt][1] * i0, h0, l0);
        split_h2(o[dt][2] * i1, o[dt][3] * i1, h1, l1);
        g_ah[row + w]  = h0;  g_al[row + w]  = l0;
        g_ah[row2 + w] = h1;  g_al[row2 + w] = l1;
    }
}

// ---------------- launcher ---------------------------------------------------
extern "C" void kernel_launch(void* const* d_in, const int* in_sizes, int n_in,
                              void* d_out, int out_size)
{
    const float* x_q = (const float*)d_in[0];
    const float* x_k = (const float*)d_in[1];
    const float* x_v = (const float*)d_in[2];
    const float* w_q = (const float*)d_in[3];
    const float* w_k = (const float*)d_in[4];
    const float* w_v = (const float*)d_in[5];
    const float* w_o = (const float*)d_in[6];
    const int*   msk = (const int*)d_in[7];
    float* out = (float*)d_out;

    cudaFuncSetAttribute((const void*)gemm_p_kernel<0,3>, cudaFuncAttributeMaxDynamicSharedMemorySize, GSM3_BYTES);
    cudaFuncSetAttribute((const void*)gemm_p_kernel<0,2>, cudaFuncAttributeMaxDynamicSharedMemorySize, GSM2_BYTES);
    cudaFuncSetAttribute((const void*)gemm_p_kernel<1,2>, cudaFuncAttributeMaxDynamicSharedMemorySize, GSM2_BYTES);
    cudaFuncSetAttribute((const void*)flash_kernel, cudaFuncAttributeMaxDynamicSharedMemorySize, FSM_BYTES);

    // one-time pre-split conversions
    conv_x_kernel<<<dim3(MROWS * 512 / 256, 1, 3), 256>>>(x_q, x_k, x_v);
    conv_w_kernel<<<dim3(512 * 1024 / 256, 4), 256>>>(w_q, w_k, w_v, w_o);

    // Q, K projections: fp16 x3
    gemm_p_kernel<0,3><<<dim3(MROWS / 128, NHEAD / 2, 2), 256, GSM3_BYTES>>>(nullptr, 0);
    // V projection: fp16 x2
    gemm_p_kernel<0,2><<<dim3(MROWS / 128, NHEAD / 2, 1), 256, GSM2_BYTES>>>(nullptr, 2);

    flash_kernel<<<dim3(SEQL / 128, BH), 256, FSM_BYTES>>>(msk);

    // Output projection: fp16 x2
    gemm_p_kernel<1,2><<<dim3(MROWS / 128, EMB / 128, 1), 256, GSM2_BYTES>>>(out, 0);
}

// round 15
// speedup vs baseline: 1.1478x; 1.1478x over previous
#include <cuda_runtime.h>
#include <cuda_fp16.h>
#include <cstdint>

#define BATCHN 4
#define SEQL   2048
#define EMB    1024
#define NHEAD  16
#define DKH    64
#define MROWS  (BATCHN*SEQL)   /* 8192 */
#define BH     (BATCHN*NHEAD)  /* 64 */

// ---------------- scratch (static device globals; no runtime allocation) ----
__device__ unsigned g_xh[3][(size_t)MROWS*512];   // x hi, [row][kpair]
__device__ unsigned g_xl[3][(size_t)MROWS*512];   // lo
__device__ unsigned g_wh[4][(size_t)1024*512];    // weights hi, [col][kpair]  (BT layout)
__device__ unsigned g_wl[2][(size_t)1024*512];    // weights lo (Q,K only)
__device__ unsigned g_qh[(size_t)BH*SEQL*32];     // q hi (scaled by 8*log2e)
__device__ unsigned g_ql[(size_t)BH*SEQL*32];
__device__ unsigned g_kh[(size_t)BH*SEQL*32];
__device__ unsigned g_kl[(size_t)BH*SEQL*32];
__device__ unsigned g_vh[(size_t)BH*SEQL*32];     // v hi only
__device__ unsigned g_ah[(size_t)MROWS*512];      // attn out hi, [row][epair]

#define LOG2E 1.4426950408889634f

// ---------------- helpers ---------------------------------------------------
__device__ __forceinline__ void mma16h(float c[4], unsigned a0, unsigned a1, unsigned a2, unsigned a3,
                                       unsigned b0, unsigned b1) {
    asm volatile(
        "mma.sync.aligned.m16n8k16.row.col.f32.f16.f16.f32 "
        "{%0,%1,%2,%3},{%4,%5,%6,%7},{%8,%9},{%0,%1,%2,%3};\n"
        : "+f"(c[0]), "+f"(c[1]), "+f"(c[2]), "+f"(c[3])
        : "r"(a0), "r"(a1), "r"(a2), "r"(a3), "r"(b0), "r"(b1));
}
__device__ __forceinline__ void ldm4(uint4 &r, uint32_t a) {
    asm volatile("ldmatrix.sync.aligned.m8n8.x4.shared.b16 {%0,%1,%2,%3}, [%4];"
                 : "=r"(r.x), "=r"(r.y), "=r"(r.z), "=r"(r.w) : "r"(a));
}
__device__ __forceinline__ void split_h2(float x0, float x1, unsigned &hi, unsigned &lo) {
    __half2 H = __floats2half2_rn(x0, x1);
    float2 f = __half22float2(H);
    __half2 L = __floats2half2_rn(x0 - f.x, x1 - f.y);
    hi = *reinterpret_cast<unsigned*>(&H);
    lo = *reinterpret_cast<unsigned*>(&L);
}
__device__ __forceinline__ unsigned pack_h2(float x0, float x1) {
    __half2 H = __floats2half2_rn(x0, x1);
    return *reinterpret_cast<unsigned*>(&H);
}
__device__ __forceinline__ uint32_t smem_u32(const void* p) {
    uint32_t a;
    asm("{ .reg .u64 t; cvta.to.shared.u64 t, %1; cvt.u32.u64 %0, t; }" : "=r"(a) : "l"(p));
    return a;
}
#define CPA16(dst, src) asm volatile("cp.async.cg.shared.global [%0], [%1], 16;" :: "r"(dst), "l"(src))
#define CPA_COMMIT()    asm volatile("cp.async.commit_group;" ::: "memory")
#define CPA_WAIT0()     asm volatile("cp.async.wait_group 0;" ::: "memory")

// ---------------- conversion kernels -----------------------------------------
__global__ void __launch_bounds__(256) conv_x_kernel(
    const float* __restrict__ x0, const float* __restrict__ x1, const float* __restrict__ x2)
{
    int sel = blockIdx.z;
    const float* x = sel == 0 ? x0 : (sel == 1 ? x1 : x2);
    size_t idx = (size_t)blockIdx.x * 256 + threadIdx.x;
    float2 v = *reinterpret_cast<const float2*>(x + 2 * idx);
    unsigned h, l;
    split_h2(v.x, v.y, h, l);
    g_xh[sel][idx] = h;
    g_xl[sel][idx] = l;
}

// weights -> split packed, BT layout: g_w[col*512 + kpair]; lo only for Q,K
__global__ void __launch_bounds__(256) conv_w_kernel(
    const float* __restrict__ w0, const float* __restrict__ w1,
    const float* __restrict__ w2, const float* __restrict__ w3)
{
    int wsel = blockIdx.y;
    const float* W = wsel == 0 ? w0 : (wsel == 1 ? w1 : (wsel == 2 ? w2 : w3));
    size_t idx = (size_t)blockIdx.x * 256 + threadIdx.x;   // < 512*1024
    int p   = (int)(idx >> 10);
    int col = (int)(idx & 1023);
    float v0, v1;
    if (wsel < 3) {
        int head = col >> 6, d = col & 63;
        size_t base = (size_t)head * EMB * 64 + (size_t)(2 * p) * 64 + d;
        v0 = W[base];
        v1 = W[base + 64];
    } else {
        v0 = W[(size_t)(2 * p) * EMB + col];
        v1 = W[(size_t)(2 * p + 1) * EMB + col];
    }
    unsigned h, l;
    split_h2(v0, v1, h, l);
    g_wh[wsel][(size_t)col * 512 + p] = h;
    if (wsel < 2) g_wl[wsel][(size_t)col * 512 + p] = l;
}

// ---------------- GEMM (pre-split fp16, ldmatrix fragments) ------------------
// A tile:  [128 rows][TW=20 kpair words] hi(+lo).
// BT tile: [128 cols][TW=20 kpair words] hi(+lo x3).
#define TW 20
#define CHUNK 32
#define GSTAGE (4*128*TW)
#define GSM_BYTES (2 * GSTAGE * 4)   /* 81920 */

template<int MODE, int PASSES>
__global__ void __launch_bounds__(256, 2) gemm_p_kernel(float* __restrict__ Cext, int selbase)
{
    constexpr int G_AH = 0;
    constexpr int G_AL = 128 * TW;
    constexpr int G_BH = 2 * 128 * TW;
    constexpr int G_BL = 3 * 128 * TW;
    constexpr int NCH = EMB / CHUNK;   // 32
    constexpr int BKP = CHUNK / 2;     // 16

    extern __shared__ unsigned smu[];
    const uint32_t sbase = smem_u32(smu);

    const int tid  = threadIdx.x;
    const int lane = tid & 31;
    const int warp = tid >> 5;
    const int wm = warp >> 1, wn = warp & 1;
    const int row0 = blockIdx.x * 128;
    const int col0 = blockIdx.y * 128;

    int sel = (MODE == 0) ? (blockIdx.z + selbase) : 3;
    const unsigned* Ahg = (MODE == 0) ? g_xh[sel] : g_ah;
    const unsigned* Alg = (MODE == 0) ? g_xl[sel] : g_ah;   // lo unused when PASSES<2
    const unsigned* Whg = g_wh[sel];
    const unsigned* Wlg = g_wl[sel < 2 ? sel : 0];           // lo unused when PASSES<3

    float acc[2][8][4];
#pragma unroll
    for (int i = 0; i < 2; i++)
#pragma unroll
        for (int j = 0; j < 8; j++)
#pragma unroll
            for (int r = 0; r < 4; r++) acc[i][j][r] = 0.f;

    const int am = tid & 127;
    const int ps = tid >> 7;

    const int a_off = (wm * 32 + (lane & 15)) * TW + (lane >> 4) * 4;
    const int b_off = (wn * 64 + ((lane >> 4) << 3) + (lane & 7)) * TW + ((lane >> 3) & 1) * 4;

    auto issue = [&](int c, int st) {
        {   // A hi (+lo)
            const unsigned* srcH = Ahg + (size_t)(row0 + am) * 512 + c * BKP + ps * 8;
            uint32_t dH = sbase + (uint32_t)(st * GSTAGE + G_AH + am * TW + ps * 8) * 4;
            CPA16(dH, srcH); CPA16(dH + 16, srcH + 4);
            if (PASSES >= 2) {
                const unsigned* srcL = Alg + (size_t)(row0 + am) * 512 + c * BKP + ps * 8;
                uint32_t dL = sbase + (uint32_t)(st * GSTAGE + G_AL + am * TW + ps * 8) * 4;
                CPA16(dL, srcL); CPA16(dL + 16, srcL + 4);
            }
        }
        {   // BT hi (+lo)
#pragma unroll
            for (int a = 0; a < 2; a++) {
                int seg = tid + a * 256;
                int cl = seg >> 2, pt = (seg & 3) * 4;
                const unsigned* srcH = Whg + (size_t)(col0 + cl) * 512 + c * BKP + pt;
                uint32_t dH = sbase + (uint32_t)(st * GSTAGE + G_BH + cl * TW + pt) * 4;
                CPA16(dH, srcH);
                if (PASSES >= 3) {
                    const unsigned* srcL = Wlg + (size_t)(col0 + cl) * 512 + c * BKP + pt;
                    uint32_t dL = sbase + (uint32_t)(st * GSTAGE + G_BL + cl * TW + pt) * 4;
                    CPA16(dL, srcL);
                }
            }
        }
        CPA_COMMIT();
    };

    issue(0, 0);

    for (int c = 0; c < NCH; c++) {
        const int st = c & 1;
        CPA_WAIT0();
        __syncthreads();
        if (c + 1 < NCH) issue(c + 1, st ^ 1);

        const uint32_t stb = sbase + (uint32_t)(st * GSTAGE) * 4;

#pragma unroll
        for (int ks = 0; ks < 2; ks++) {
            const int kw = ks * 8;
            uint4 ah[2], al[2];
#pragma unroll
            for (int mt = 0; mt < 2; mt++) {
                uint32_t aw = stb + (uint32_t)(a_off + mt * 16 * TW + kw) * 4;
                ldm4(ah[mt], aw + G_AH * 4);
                if (PASSES >= 2) ldm4(al[mt], aw + G_AL * 4);
            }
#pragma unroll
            for (int ntp = 0; ntp < 4; ntp++) {
                uint32_t bw = stb + (uint32_t)(b_off + ntp * 16 * TW + kw) * 4;
                uint4 bh; ldm4(bh, bw + G_BH * 4);
#pragma unroll
                for (int mt = 0; mt < 2; mt++) {
                    mma16h(acc[mt][2*ntp],   ah[mt].x, ah[mt].y, ah[mt].z, ah[mt].w, bh.x, bh.y);
                    mma16h(acc[mt][2*ntp+1], ah[mt].x, ah[mt].y, ah[mt].z, ah[mt].w, bh.z, bh.w);
                    if (PASSES >= 2) {
                        mma16h(acc[mt][2*ntp],   al[mt].x, al[mt].y, al[mt].z, al[mt].w, bh.x, bh.y);
                        mma16h(acc[mt][2*ntp+1], al[mt].x, al[mt].y, al[mt].z, al[mt].w, bh.z, bh.w);
                    }
                }
                if (PASSES >= 3) {
                    uint4 bl; ldm4(bl, bw + G_BL * 4);
#pragma unroll
                    for (int mt = 0; mt < 2; mt++) {
                        mma16h(acc[mt][2*ntp],   ah[mt].x, ah[mt].y, ah[mt].z, ah[mt].w, bl.x, bl.y);
                        mma16h(acc[mt][2*ntp+1], ah[mt].x, ah[mt].y, ah[mt].z, ah[mt].w, bl.z, bl.w);
                    }
                }
            }
        }
        __syncthreads();
    }

    // ---- epilogue ----
    const float qscale = 8.f * LOG2E;
    const int r8 = lane >> 2, lq = lane & 3;
#pragma unroll
    for (int mt = 0; mt < 2; mt++) {
        int r = row0 + wm * 32 + mt * 16 + r8;
#pragma unroll
        for (int nt = 0; nt < 8; nt++) {
            int cc = wn * 64 + nt * 8 + lq * 2;
            if (MODE == 0) {
                int b = r >> 11, s = r & 2047;
                int head = blockIdx.y * 2 + (cc >> 6);
                int w = (cc & 63) >> 1;
                size_t widx  = ((size_t)(b * NHEAD + head) * SEQL + s) * 32 + w;
                size_t widx2 = widx + (size_t)8 * 32;
                float v0 = acc[mt][nt][0], v1 = acc[mt][nt][1];
                float v2 = acc[mt][nt][2], v3 = acc[mt][nt][3];
                if (sel == 0) { v0 *= qscale; v1 *= qscale; v2 *= qscale; v3 *= qscale; }
                unsigned h0, l0, h1, l1;
                split_h2(v0, v1, h0, l0);
                split_h2(v2, v3, h1, l1);
                if (sel == 0) {
                    g_qh[widx] = h0;  g_ql[widx] = l0;
                    g_qh[widx2] = h1; g_ql[widx2] = l1;
                } else if (sel == 1) {
                    g_kh[widx] = h0;  g_kl[widx] = l0;
                    g_kh[widx2] = h1; g_kl[widx2] = l1;
                } else {
                    g_vh[widx] = h0;
                    g_vh[widx2] = h1;
                }
            } else {
                size_t base = (size_t)r * EMB + col0 + cc;
                Cext[base]               = acc[mt][nt][0];
                Cext[base + 1]           = acc[mt][nt][1];
                Cext[base + 8 * EMB]     = acc[mt][nt][2];
                Cext[base + 8 * EMB + 1] = acc[mt][nt][3];
            }
        }
    }
}

// ---------------- flash attention (causal), pre-split fp16 -------------------
#define QW 36
#define KW 36
#define PW 68
#define FQ_H 0
#define FQ_L (128*QW)
#define FK_H 0
#define FK_L (64*KW)
#define FV_H (2*64*KW)
#define FSM_WORDS (2*128*QW)
#define FSM_BYTES (FSM_WORDS*4)

__global__ void __launch_bounds__(256) flash_kernel(const int* __restrict__ maskp)
{
    extern __shared__ unsigned smw[];

    const int tid  = threadIdx.x;
    const int lane = tid & 31;
    const int warp = tid >> 5;
    const int r8 = lane >> 2, lq = lane & 3;
    const int qt = blockIdx.x;
    const int bh = blockIdx.y;
    const int b = bh >> 4, h = bh & 15;
    const int q0 = qt * 128;
    const size_t sb = (size_t)bh * SEQL;

#pragma unroll
    for (int ii = 0; ii < 4; ii++) {
        int i = tid + ii * 256;
        int r = i >> 3, sg = (i & 7) * 4;
        uint4 vh = *reinterpret_cast<const uint4*>(g_qh + (sb + q0 + r) * 32 + sg);
        uint4 vl = *reinterpret_cast<const uint4*>(g_ql + (sb + q0 + r) * 32 + sg);
        *reinterpret_cast<uint4*>(smw + FQ_H + r * QW + sg) = vh;
        *reinterpret_cast<uint4*>(smw + FQ_L + r * QW + sg) = vl;
    }
    __syncthreads();

    const int rl = warp * 16 + r8;
    unsigned qh[4][4], ql[4][4];
#pragma unroll
    for (int ks = 0; ks < 4; ks++) {
        int base = rl * QW + ks * 8 + lq;
        qh[ks][0] = smw[FQ_H + base];
        qh[ks][1] = smw[FQ_H + base + 8 * QW];
        qh[ks][2] = smw[FQ_H + base + 4];
        qh[ks][3] = smw[FQ_H + base + 8 * QW + 4];
        ql[ks][0] = smw[FQ_L + base];
        ql[ks][1] = smw[FQ_L + base + 8 * QW];
        ql[ks][2] = smw[FQ_L + base + 4];
        ql[ks][3] = smw[FQ_L + base + 8 * QW + 4];
    }
    __syncthreads();

    float m[2] = { -1e30f, -1e30f };
    float l[2] = { 0.f, 0.f };
    float o[8][4];
#pragma unroll
    for (int i = 0; i < 8; i++)
#pragma unroll
        for (int j = 0; j < 4; j++) o[i][j] = 0.f;

    const int maskv = maskp[0];
    const int tdiag = 2 * qt + (warp >> 2);
    const int ntiles = maskv ? (2 * qt + 2) : (SEQL / 64);

    __half* vhp = reinterpret_cast<__half*>(smw + FV_H);

    for (int t = 0; t < ntiles; t++) {
        const int kv0 = t * 64;

        if (t > 0) __syncthreads();
#pragma unroll
        for (int ii = 0; ii < 2; ii++) {
            int i = tid + ii * 256;
            int r = i >> 3, sg = (i & 7) * 4;
            uint4 vh = *reinterpret_cast<const uint4*>(g_kh + (sb + kv0 + r) * 32 + sg);
            uint4 vl = *reinterpret_cast<const uint4*>(g_kl + (sb + kv0 + r) * 32 + sg);
            *reinterpret_cast<uint4*>(smw + FK_H + r * KW + sg) = vh;
            *reinterpret_cast<uint4*>(smw + FK_L + r * KW + sg) = vl;
        }
#pragma unroll
        for (int ii = 0; ii < 4; ii++) {
            int i = tid + ii * 256;
            int r = i >> 4, c4 = (i & 15) << 2;
            uint2 w2 = *reinterpret_cast<const uint2*>(g_vh + (sb + kv0 + r) * 32 + (c4 >> 1));
            __half2 p0 = *reinterpret_cast<__half2*>(&w2.x);
            __half2 p1 = *reinterpret_cast<__half2*>(&w2.y);
            int p = r >> 1, rb = r & 1;
            vhp[(p * PW + c4 + 0) * 2 + rb] = __low2half(p0);
            vhp[(p * PW + c4 + 1) * 2 + rb] = __high2half(p0);
            vhp[(p * PW + c4 + 2) * 2 + rb] = __low2half(p1);
            vhp[(p * PW + c4 + 3) * 2 + rb] = __high2half(p1);
        }
        __syncthreads();

        if (maskv && t > tdiag) continue;

        float s[8][4];
#pragma unroll
        for (int i = 0; i < 8; i++)
#pragma unroll
            for (int j = 0; j < 4; j++) s[i][j] = 0.f;

#pragma unroll
        for (int ks = 0; ks < 4; ks++) {
#pragma unroll
            for (int nt = 0; nt < 8; nt++) {
                int n = nt * 8 + r8;
                unsigned bh0 = smw[FK_H + n * KW + ks * 8 + lq];
                unsigned bh1 = smw[FK_H + n * KW + ks * 8 + lq + 4];
                unsigned bl0 = smw[FK_L + n * KW + ks * 8 + lq];
                unsigned bl1 = smw[FK_L + n * KW + ks * 8 + lq + 4];
                mma16h(s[nt], qh[ks][0], qh[ks][1], qh[ks][2], qh[ks][3], bh0, bh1);
                mma16h(s[nt], qh[ks][0], qh[ks][1], qh[ks][2], qh[ks][3], bl0, bl1);
                mma16h(s[nt], ql[ks][0], ql[ks][1], ql[ks][2], ql[ks][3], bh0, bh1);
            }
        }

        if (maskv && t == tdiag) {
            int rg0 = q0 + rl;
#pragma unroll
            for (int nt = 0; nt < 8; nt++) {
                int cg = kv0 + nt * 8 + lq * 2;
                if (cg > rg0)         s[nt][0] = -1e30f;
                if (cg + 1 > rg0)     s[nt][1] = -1e30f;
                if (cg > rg0 + 8)     s[nt][2] = -1e30f;
                if (cg + 1 > rg0 + 8) s[nt][3] = -1e30f;
            }
        }

#pragma unroll
        for (int sub = 0; sub < 2; sub++) {
            float tm = -1e30f;
#pragma unroll
            for (int nt = 0; nt < 8; nt++)
                tm = fmaxf(tm, fmaxf(s[nt][2 * sub], s[nt][2 * sub + 1]));
            tm = fmaxf(tm, __shfl_xor_sync(0xffffffffu, tm, 1));
            tm = fmaxf(tm, __shfl_xor_sync(0xffffffffu, tm, 2));
            float mn = fmaxf(m[sub], tm);
            float alpha = exp2f(m[sub] - mn);
            float rs = 0.f;
#pragma unroll
            for (int nt = 0; nt < 8; nt++) {
                float p0 = exp2f(s[nt][2 * sub] - mn);
                float p1 = exp2f(s[nt][2 * sub + 1] - mn);
                s[nt][2 * sub] = p0; s[nt][2 * sub + 1] = p1;
                rs += p0 + p1;
            }
            rs += __shfl_xor_sync(0xffffffffu, rs, 1);
            rs += __shfl_xor_sync(0xffffffffu, rs, 2);
            l[sub] = l[sub] * alpha + rs;
            m[sub] = mn;
#pragma unroll
            for (int dt = 0; dt < 8; dt++) {
                o[dt][2 * sub]     *= alpha;
                o[dt][2 * sub + 1] *= alpha;
            }
        }

        unsigned pa[4][4];
#pragma unroll
        for (int ks = 0; ks < 4; ks++) {
            pa[ks][0] = pack_h2(s[2*ks][0],   s[2*ks][1]);
            pa[ks][1] = pack_h2(s[2*ks][2],   s[2*ks][3]);
            pa[ks][2] = pack_h2(s[2*ks+1][0], s[2*ks+1][1]);
            pa[ks][3] = pack_h2(s[2*ks+1][2], s[2*ks+1][3]);
        }

        int ksmax = (maskv && t == tdiag) ? ((warp & 3) + 1) : 4;
#pragma unroll
        for (int ks = 0; ks < 4; ks++) {
            if (ks >= ksmax) break;
#pragma unroll
            for (int dt = 0; dt < 8; dt++) {
                int d = dt * 8 + r8;
                unsigned bh0 = smw[FV_H + (ks * 8 + lq) * PW + d];
                unsigned bh1 = smw[FV_H + (ks * 8 + lq + 4) * PW + d];
                mma16h(o[dt], pa[ks][0], pa[ks][1], pa[ks][2], pa[ks][3], bh0, bh1);
            }
        }
    }

    // ---- epilogue: attn output hi-only (out-proj is x1) ----
    float i0 = 1.f / l[0];
    float i1 = 1.f / l[1];
    int rg = q0 + rl;
    size_t row  = (size_t)(b * SEQL + rg) * 512;
    size_t row2 = row + (size_t)8 * 512;
#pragma unroll
    for (int dt = 0; dt < 8; dt++) {
        int w = h * 32 + dt * 4 + lq;
        g_ah[row + w]  = pack_h2(o[dt][0] * i0, o[dt][1] * i0);
        g_ah[row2 + w] = pack_h2(o[dt][2] * i1, o[dt][3] * i1);
    }
}

// ---------------- launcher ---------------------------------------------------
extern "C" void kernel_launch(void* const* d_in, const int* in_sizes, int n_in,
                              void* d_out, int out_size)
{
    const float* x_q = (const float*)d_in[0];
    const float* x_k = (const float*)d_in[1];
    const float* x_v = (const float*)d_in[2];
    const float* w_q = (const float*)d_in[3];
    const float* w_k = (const float*)d_in[4];
    const float* w_v = (const float*)d_in[5];
    const float* w_o = (const float*)d_in[6];
    const int*   msk = (const int*)d_in[7];
    float* out = (float*)d_out;

    cudaFuncSetAttribute((const void*)gemm_p_kernel<0,3>, cudaFuncAttributeMaxDynamicSharedMemorySize, GSM_BYTES);
    cudaFuncSetAttribute((const void*)gemm_p_kernel<0,1>, cudaFuncAttributeMaxDynamicSharedMemorySize, GSM_BYTES);
    cudaFuncSetAttribute((const void*)gemm_p_kernel<1,1>, cudaFuncAttributeMaxDynamicSharedMemorySize, GSM_BYTES);
    cudaFuncSetAttribute((const void*)flash_kernel, cudaFuncAttributeMaxDynamicSharedMemorySize, FSM_BYTES);

    // one-time pre-split conversions
    conv_x_kernel<<<dim3(MROWS * 512 / 256, 1, 3), 256>>>(x_q, x_k, x_v);
    conv_w_kernel<<<dim3(512 * 1024 / 256, 4), 256>>>(w_q, w_k, w_v, w_o);

    // Q, K projections: fp16 x3 (score path needs 2^-22)
    gemm_p_kernel<0,3><<<dim3(MROWS / 128, NHEAD / 2, 2), 256, GSM_BYTES>>>(nullptr, 0);
    // V projection: fp16 x1 (result is fp16-quantized anyway)
    gemm_p_kernel<0,1><<<dim3(MROWS / 128, NHEAD / 2, 1), 256, GSM_BYTES>>>(nullptr, 2);

    flash_kernel<<<dim3(SEQL / 128, BH), 256, FSM_BYTES>>>(msk);

    // Output projection: fp16 x1 (decorrelated rounding, ~2-3e-4 rel)
    gemm_p_kernel<1,1><<<dim3(MROWS / 128, EMB / 128, 1), 256, GSM_BYTES>>>(out, 0);
}

// round 16
// speedup vs baseline: 1.1586x; 1.0094x over previous
#include <cuda_runtime.h>
#include <cuda_fp16.h>
#include <cstdint>

#define BATCHN 4
#define SEQL   2048
#define EMB    1024
#define NHEAD  16
#define DKH    64
#define MROWS  (BATCHN*SEQL)   /* 8192 */
#define BH     (BATCHN*NHEAD)  /* 64 */

// ---------------- scratch (static device globals; no runtime allocation) ----
__device__ unsigned g_xh[3][(size_t)MROWS*512];   // x hi, [row][kpair]
__device__ unsigned g_xl[3][(size_t)MROWS*512];   // lo
__device__ unsigned g_wh[4][(size_t)1024*512];    // weights hi, [col][kpair]  (BT layout)
__device__ unsigned g_wl[2][(size_t)1024*512];    // weights lo (Q,K only)
__device__ unsigned g_qh[(size_t)BH*SEQL*32];     // q hi (scaled by 8*log2e)
__device__ unsigned g_ql[(size_t)BH*SEQL*32];
__device__ unsigned g_kh[(size_t)BH*SEQL*32];
__device__ unsigned g_kl[(size_t)BH*SEQL*32];
__device__ unsigned g_vh[(size_t)BH*SEQL*32];     // v hi only
__device__ unsigned g_ah[(size_t)MROWS*512];      // attn out hi, [row][epair]

#define LOG2E 1.4426950408889634f

// ---------------- helpers ---------------------------------------------------
__device__ __forceinline__ void mma16h(float c[4], unsigned a0, unsigned a1, unsigned a2, unsigned a3,
                                       unsigned b0, unsigned b1) {
    asm volatile(
        "mma.sync.aligned.m16n8k16.row.col.f32.f16.f16.f32 "
        "{%0,%1,%2,%3},{%4,%5,%6,%7},{%8,%9},{%0,%1,%2,%3};\n"
        : "+f"(c[0]), "+f"(c[1]), "+f"(c[2]), "+f"(c[3])
        : "r"(a0), "r"(a1), "r"(a2), "r"(a3), "r"(b0), "r"(b1));
}
__device__ __forceinline__ void ldm4(uint4 &r, uint32_t a) {
    asm volatile("ldmatrix.sync.aligned.m8n8.x4.shared.b16 {%0,%1,%2,%3}, [%4];"
                 : "=r"(r.x), "=r"(r.y), "=r"(r.z), "=r"(r.w) : "r"(a));
}
__device__ __forceinline__ void split_h2(float x0, float x1, unsigned &hi, unsigned &lo) {
    __half2 H = __floats2half2_rn(x0, x1);
    float2 f = __half22float2(H);
    __half2 L = __floats2half2_rn(x0 - f.x, x1 - f.y);
    hi = *reinterpret_cast<unsigned*>(&H);
    lo = *reinterpret_cast<unsigned*>(&L);
}
__device__ __forceinline__ unsigned pack_h2(float x0, float x1) {
    __half2 H = __floats2half2_rn(x0, x1);
    return *reinterpret_cast<unsigned*>(&H);
}
__device__ __forceinline__ uint32_t smem_u32(const void* p) {
    uint32_t a;
    asm("{ .reg .u64 t; cvta.to.shared.u64 t, %1; cvt.u32.u64 %0, t; }" : "=r"(a) : "l"(p));
    return a;
}
#define CPA16(dst, src) asm volatile("cp.async.cg.shared.global [%0], [%1], 16;" :: "r"(dst), "l"(src))
#define CPA_COMMIT()    asm volatile("cp.async.commit_group;" ::: "memory")
#define CPA_WAIT0()     asm volatile("cp.async.wait_group 0;" ::: "memory")

// ---------------- conversion kernels -----------------------------------------
__global__ void __launch_bounds__(256) conv_x_kernel(
    const float* __restrict__ x0, const float* __restrict__ x1, const float* __restrict__ x2)
{
    int sel = blockIdx.z;
    const float* x = sel == 0 ? x0 : (sel == 1 ? x1 : x2);
    size_t idx = (size_t)blockIdx.x * 256 + threadIdx.x;
    float2 v = *reinterpret_cast<const float2*>(x + 2 * idx);
    unsigned h, l;
    split_h2(v.x, v.y, h, l);
    g_xh[sel][idx] = h;
    g_xl[sel][idx] = l;
}

__global__ void __launch_bounds__(256) conv_w_kernel(
    const float* __restrict__ w0, const float* __restrict__ w1,
    const float* __restrict__ w2, const float* __restrict__ w3)
{
    int wsel = blockIdx.y;
    const float* W = wsel == 0 ? w0 : (wsel == 1 ? w1 : (wsel == 2 ? w2 : w3));
    size_t idx = (size_t)blockIdx.x * 256 + threadIdx.x;
    int p   = (int)(idx >> 10);
    int col = (int)(idx & 1023);
    float v0, v1;
    if (wsel < 3) {
        int head = col >> 6, d = col & 63;
        size_t base = (size_t)head * EMB * 64 + (size_t)(2 * p) * 64 + d;
        v0 = W[base];
        v1 = W[base + 64];
    } else {
        v0 = W[(size_t)(2 * p) * EMB + col];
        v1 = W[(size_t)(2 * p + 1) * EMB + col];
    }
    unsigned h, l;
    split_h2(v0, v1, h, l);
    g_wh[wsel][(size_t)col * 512 + p] = h;
    if (wsel < 2) g_wl[wsel][(size_t)col * 512 + p] = l;
}

// ---------------- GEMM body (pre-split fp16, ldmatrix fragments) -------------
#define TW 20
#define CHUNK 32
#define GSTAGE (4*128*TW)
#define GSM_BYTES (2 * GSTAGE * 4)   /* 81920 */

template<int MODE, int PASSES>
__device__ __forceinline__ void gemm_body(unsigned* smu, float* __restrict__ Cext, int sel)
{
    constexpr int G_AH = 0;
    constexpr int G_AL = 128 * TW;
    constexpr int G_BH = 2 * 128 * TW;
    constexpr int G_BL = 3 * 128 * TW;
    constexpr int NCH = EMB / CHUNK;   // 32
    constexpr int BKP = CHUNK / 2;     // 16

    const uint32_t sbase = smem_u32(smu);

    const int tid  = threadIdx.x;
    const int lane = tid & 31;
    const int warp = tid >> 5;
    const int wm = warp >> 1, wn = warp & 1;
    const int row0 = blockIdx.x * 128;
    const int col0 = blockIdx.y * 128;

    const unsigned* Ahg = (MODE == 0) ? g_xh[sel] : g_ah;
    const unsigned* Alg = (MODE == 0) ? g_xl[sel] : g_ah;   // unused if PASSES<2
    const unsigned* Whg = g_wh[sel];
    const unsigned* Wlg = g_wl[sel < 2 ? sel : 0];           // unused if PASSES<3

    float acc[2][8][4];
#pragma unroll
    for (int i = 0; i < 2; i++)
#pragma unroll
        for (int j = 0; j < 8; j++)
#pragma unroll
            for (int r = 0; r < 4; r++) acc[i][j][r] = 0.f;

    const int am = tid & 127;
    const int ps = tid >> 7;

    const int a_off = (wm * 32 + (lane & 15)) * TW + (lane >> 4) * 4;
    const int b_off = (wn * 64 + ((lane >> 4) << 3) + (lane & 7)) * TW + ((lane >> 3) & 1) * 4;

    auto issue = [&](int c, int st) {
        {
            const unsigned* srcH = Ahg + (size_t)(row0 + am) * 512 + c * BKP + ps * 8;
            uint32_t dH = sbase + (uint32_t)(st * GSTAGE + G_AH + am * TW + ps * 8) * 4;
            CPA16(dH, srcH); CPA16(dH + 16, srcH + 4);
            if (PASSES >= 2) {
                const unsigned* srcL = Alg + (size_t)(row0 + am) * 512 + c * BKP + ps * 8;
                uint32_t dL = sbase + (uint32_t)(st * GSTAGE + G_AL + am * TW + ps * 8) * 4;
                CPA16(dL, srcL); CPA16(dL + 16, srcL + 4);
            }
        }
        {
#pragma unroll
            for (int a = 0; a < 2; a++) {
                int seg = tid + a * 256;
                int cl = seg >> 2, pt = (seg & 3) * 4;
                const unsigned* srcH = Whg + (size_t)(col0 + cl) * 512 + c * BKP + pt;
                uint32_t dH = sbase + (uint32_t)(st * GSTAGE + G_BH + cl * TW + pt) * 4;
                CPA16(dH, srcH);
                if (PASSES >= 3) {
                    const unsigned* srcL = Wlg + (size_t)(col0 + cl) * 512 + c * BKP + pt;
                    uint32_t dL = sbase + (uint32_t)(st * GSTAGE + G_BL + cl * TW + pt) * 4;
                    CPA16(dL, srcL);
                }
            }
        }
        CPA_COMMIT();
    };

    issue(0, 0);

    for (int c = 0; c < NCH; c++) {
        const int st = c & 1;
        CPA_WAIT0();
        __syncthreads();
        if (c + 1 < NCH) issue(c + 1, st ^ 1);

        const uint32_t stb = sbase + (uint32_t)(st * GSTAGE) * 4;

#pragma unroll
        for (int ks = 0; ks < 2; ks++) {
            const int kw = ks * 8;
            uint4 ah[2], al[2];
#pragma unroll
            for (int mt = 0; mt < 2; mt++) {
                uint32_t aw = stb + (uint32_t)(a_off + mt * 16 * TW + kw) * 4;
                ldm4(ah[mt], aw + G_AH * 4);
                if (PASSES >= 2) ldm4(al[mt], aw + G_AL * 4);
            }
#pragma unroll
            for (int ntp = 0; ntp < 4; ntp++) {
                uint32_t bw = stb + (uint32_t)(b_off + ntp * 16 * TW + kw) * 4;
                uint4 bh; ldm4(bh, bw + G_BH * 4);
#pragma unroll
                for (int mt = 0; mt < 2; mt++) {
                    mma16h(acc[mt][2*ntp],   ah[mt].x, ah[mt].y, ah[mt].z, ah[mt].w, bh.x, bh.y);
                    mma16h(acc[mt][2*ntp+1], ah[mt].x, ah[mt].y, ah[mt].z, ah[mt].w, bh.z, bh.w);
                    if (PASSES >= 2) {
                        mma16h(acc[mt][2*ntp],   al[mt].x, al[mt].y, al[mt].z, al[mt].w, bh.x, bh.y);
                        mma16h(acc[mt][2*ntp+1], al[mt].x, al[mt].y, al[mt].z, al[mt].w, bh.z, bh.w);
                    }
                }
                if (PASSES >= 3) {
                    uint4 bl; ldm4(bl, bw + G_BL * 4);
#pragma unroll
                    for (int mt = 0; mt < 2; mt++) {
                        mma16h(acc[mt][2*ntp],   ah[mt].x, ah[mt].y, ah[mt].z, ah[mt].w, bl.x, bl.y);
                        mma16h(acc[mt][2*ntp+1], ah[mt].x, ah[mt].y, ah[mt].z, ah[mt].w, bl.z, bl.w);
                    }
                }
            }
        }
        __syncthreads();
    }

    // ---- epilogue ----
    const float qscale = 8.f * LOG2E;
    const int r8 = lane >> 2, lq = lane & 3;
#pragma unroll
    for (int mt = 0; mt < 2; mt++) {
        int r = row0 + wm * 32 + mt * 16 + r8;
#pragma unroll
        for (int nt = 0; nt < 8; nt++) {
            int cc = wn * 64 + nt * 8 + lq * 2;
            if (MODE == 0) {
                int b = r >> 11, s = r & 2047;
                int head = blockIdx.y * 2 + (cc >> 6);
                int w = (cc & 63) >> 1;
                size_t widx  = ((size_t)(b * NHEAD + head) * SEQL + s) * 32 + w;
                size_t widx2 = widx + (size_t)8 * 32;
                float v0 = acc[mt][nt][0], v1 = acc[mt][nt][1];
                float v2 = acc[mt][nt][2], v3 = acc[mt][nt][3];
                if (sel == 0) { v0 *= qscale; v1 *= qscale; v2 *= qscale; v3 *= qscale; }
                unsigned h0, l0, h1, l1;
                split_h2(v0, v1, h0, l0);
                split_h2(v2, v3, h1, l1);
                if (sel == 0) {
                    g_qh[widx] = h0;  g_ql[widx] = l0;
                    g_qh[widx2] = h1; g_ql[widx2] = l1;
                } else if (sel == 1) {
                    g_kh[widx] = h0;  g_kl[widx] = l0;
                    g_kh[widx2] = h1; g_kl[widx2] = l1;
                } else {
                    g_vh[widx] = h0;
                    g_vh[widx2] = h1;
                }
            } else {
                size_t base = (size_t)r * EMB + col0 + cc;
                Cext[base]               = acc[mt][nt][0];
                Cext[base + 1]           = acc[mt][nt][1];
                Cext[base + 8 * EMB]     = acc[mt][nt][2];
                Cext[base + 8 * EMB + 1] = acc[mt][nt][3];
            }
        }
    }
}

// fused Q/K/V projection launch: z = 0/1 -> x3 path, z = 2 -> x1 path
__global__ void __launch_bounds__(256, 2) proj_kernel()
{
    extern __shared__ unsigned smu[];
    int sel = blockIdx.z;
    if (sel < 2) gemm_body<0, 3>(smu, nullptr, sel);
    else         gemm_body<0, 1>(smu, nullptr, 2);
}

__global__ void __launch_bounds__(256, 2) outproj_kernel(float* __restrict__ Cext)
{
    extern __shared__ unsigned smu[];
    gemm_body<1, 1>(smu, Cext, 3);
}

// ---------------- flash attention (causal), pre-split fp16 -------------------
#define QW 36
#define KW 36
#define PW 68
#define FQ_H 0
#define FQ_L (128*QW)
#define FK_H 0
#define FK_L (64*KW)
#define FV_H (2*64*KW)
#define FSM_WORDS (2*128*QW)
#define FSM_BYTES (FSM_WORDS*4)

__global__ void __launch_bounds__(256) flash_kernel(const int* __restrict__ maskp)
{
    extern __shared__ unsigned smw[];

    const int tid  = threadIdx.x;
    const int lane = tid & 31;
    const int warp = tid >> 5;
    const int r8 = lane >> 2, lq = lane & 3;
    const int qt = blockIdx.x;
    const int bh = blockIdx.y;
    const int b = bh >> 4, h = bh & 15;
    const int q0 = qt * 128;
    const size_t sb = (size_t)bh * SEQL;

#pragma unroll
    for (int ii = 0; ii < 4; ii++) {
        int i = tid + ii * 256;
        int r = i >> 3, sg = (i & 7) * 4;
        uint4 vh = *reinterpret_cast<const uint4*>(g_qh + (sb + q0 + r) * 32 + sg);
        uint4 vl = *reinterpret_cast<const uint4*>(g_ql + (sb + q0 + r) * 32 + sg);
        *reinterpret_cast<uint4*>(smw + FQ_H + r * QW + sg) = vh;
        *reinterpret_cast<uint4*>(smw + FQ_L + r * QW + sg) = vl;
    }
    __syncthreads();

    const int rl = warp * 16 + r8;
    unsigned qh[4][4], ql[4][4];
#pragma unroll
    for (int ks = 0; ks < 4; ks++) {
        int base = rl * QW + ks * 8 + lq;
        qh[ks][0] = smw[FQ_H + base];
        qh[ks][1] = smw[FQ_H + base + 8 * QW];
        qh[ks][2] = smw[FQ_H + base + 4];
        qh[ks][3] = smw[FQ_H + base + 8 * QW + 4];
        ql[ks][0] = smw[FQ_L + base];
        ql[ks][1] = smw[FQ_L + base + 8 * QW];
        ql[ks][2] = smw[FQ_L + base + 4];
        ql[ks][3] = smw[FQ_L + base + 8 * QW + 4];
    }
    __syncthreads();

    float m[2] = { -1e30f, -1e30f };
    float l[2] = { 0.f, 0.f };
    float o[8][4];
#pragma unroll
    for (int i = 0; i < 8; i++)
#pragma unroll
        for (int j = 0; j < 4; j++) o[i][j] = 0.f;

    const int maskv = maskp[0];
    const int tdiag = 2 * qt + (warp >> 2);
    const int ntiles = maskv ? (2 * qt + 2) : (SEQL / 64);

    __half* vhp = reinterpret_cast<__half*>(smw + FV_H);

    for (int t = 0; t < ntiles; t++) {
        const int kv0 = t * 64;

        if (t > 0) __syncthreads();
#pragma unroll
        for (int ii = 0; ii < 2; ii++) {
            int i = tid + ii * 256;
            int r = i >> 3, sg = (i & 7) * 4;
            uint4 vh = *reinterpret_cast<const uint4*>(g_kh + (sb + kv0 + r) * 32 + sg);
            uint4 vl = *reinterpret_cast<const uint4*>(g_kl + (sb + kv0 + r) * 32 + sg);
            *reinterpret_cast<uint4*>(smw + FK_H + r * KW + sg) = vh;
            *reinterpret_cast<uint4*>(smw + FK_L + r * KW + sg) = vl;
        }
#pragma unroll
        for (int ii = 0; ii < 4; ii++) {
            int i = tid + ii * 256;
            int r = i >> 4, c4 = (i & 15) << 2;
            uint2 w2 = *reinterpret_cast<const uint2*>(g_vh + (sb + kv0 + r) * 32 + (c4 >> 1));
            __half2 p0 = *reinterpret_cast<__half2*>(&w2.x);
            __half2 p1 = *reinterpret_cast<__half2*>(&w2.y);
            int p = r >> 1, rb = r & 1;
            vhp[(p * PW + c4 + 0) * 2 + rb] = __low2half(p0);
            vhp[(p * PW + c4 + 1) * 2 + rb] = __high2half(p0);
            vhp[(p * PW + c4 + 2) * 2 + rb] = __low2half(p1);
            vhp[(p * PW + c4 + 3) * 2 + rb] = __high2half(p1);
        }
        __syncthreads();

        if (maskv && t > tdiag) continue;

        float s[8][4];
#pragma unroll
        for (int i = 0; i < 8; i++)
#pragma unroll
            for (int j = 0; j < 4; j++) s[i][j] = 0.f;

        // on the diagonal tile, nt-tiles with nt >= 2*(warp&3)+2 are fully masked
        const int ntmax = (maskv && t == tdiag) ? (2 * (warp & 3) + 2) : 8;
#pragma unroll
        for (int ks = 0; ks < 4; ks++) {
#pragma unroll
            for (int nt = 0; nt < 8; nt++) {
                if (nt >= ntmax) break;
                int n = nt * 8 + r8;
                unsigned bh0 = smw[FK_H + n * KW + ks * 8 + lq];
                unsigned bh1 = smw[FK_H + n * KW + ks * 8 + lq + 4];
                unsigned bl0 = smw[FK_L + n * KW + ks * 8 + lq];
                unsigned bl1 = smw[FK_L + n * KW + ks * 8 + lq + 4];
                mma16h(s[nt], qh[ks][0], qh[ks][1], qh[ks][2], qh[ks][3], bh0, bh1);
                mma16h(s[nt], qh[ks][0], qh[ks][1], qh[ks][2], qh[ks][3], bl0, bl1);
                mma16h(s[nt], ql[ks][0], ql[ks][1], ql[ks][2], ql[ks][3], bh0, bh1);
            }
        }

        if (maskv && t == tdiag) {
            int rg0 = q0 + rl;
#pragma unroll
            for (int nt = 0; nt < 8; nt++) {
                int cg = kv0 + nt * 8 + lq * 2;
                if (cg > rg0)         s[nt][0] = -1e30f;
                if (cg + 1 > rg0)     s[nt][1] = -1e30f;
                if (cg > rg0 + 8)     s[nt][2] = -1e30f;
                if (cg + 1 > rg0 + 8) s[nt][3] = -1e30f;
            }
        }

#pragma unroll
        for (int sub = 0; sub < 2; sub++) {
            float tm = -1e30f;
#pragma unroll
            for (int nt = 0; nt < 8; nt++)
                tm = fmaxf(tm, fmaxf(s[nt][2 * sub], s[nt][2 * sub + 1]));
            tm = fmaxf(tm, __shfl_xor_sync(0xffffffffu, tm, 1));
            tm = fmaxf(tm, __shfl_xor_sync(0xffffffffu, tm, 2));
            float mn = fmaxf(m[sub], tm);
            float alpha = exp2f(m[sub] - mn);
            float rs = 0.f;
#pragma unroll
            for (int nt = 0; nt < 8; nt++) {
                float p0 = exp2f(s[nt][2 * sub] - mn);
                float p1 = exp2f(s[nt][2 * sub + 1] - mn);
                s[nt][2 * sub] = p0; s[nt][2 * sub + 1] = p1;
                rs += p0 + p1;
            }
            rs += __shfl_xor_sync(0xffffffffu, rs, 1);
            rs += __shfl_xor_sync(0xffffffffu, rs, 2);
            l[sub] = l[sub] * alpha + rs;
            m[sub] = mn;
#pragma unroll
            for (int dt = 0; dt < 8; dt++) {
                o[dt][2 * sub]     *= alpha;
                o[dt][2 * sub + 1] *= alpha;
            }
        }

        unsigned pa[4][4];
#pragma unroll
        for (int ks = 0; ks < 4; ks++) {
            pa[ks][0] = pack_h2(s[2*ks][0],   s[2*ks][1]);
            pa[ks][1] = pack_h2(s[2*ks][2],   s[2*ks][3]);
            pa[ks][2] = pack_h2(s[2*ks+1][0], s[2*ks+1][1]);
            pa[ks][3] = pack_h2(s[2*ks+1][2], s[2*ks+1][3]);
        }

        int ksmax = (maskv && t == tdiag) ? ((warp & 3) + 1) : 4;
#pragma unroll
        for (int ks = 0; ks < 4; ks++) {
            if (ks >= ksmax) break;
#pragma unroll
            for (int dt = 0; dt < 8; dt++) {
                int d = dt * 8 + r8;
                unsigned bh0 = smw[FV_H + (ks * 8 + lq) * PW + d];
                unsigned bh1 = smw[FV_H + (ks * 8 + lq + 4) * PW + d];
                mma16h(o[dt], pa[ks][0], pa[ks][1], pa[ks][2], pa[ks][3], bh0, bh1);
            }
        }
    }

    // ---- epilogue: attn output hi-only (out-proj is x1) ----
    float i0 = 1.f / l[0];
    float i1 = 1.f / l[1];
    int rg = q0 + rl;
    size_t row  = (size_t)(b * SEQL + rg) * 512;
    size_t row2 = row + (size_t)8 * 512;
#pragma unroll
    for (int dt = 0; dt < 8; dt++) {
        int w = h * 32 + dt * 4 + lq;
        g_ah[row + w]  = pack_h2(o[dt][0] * i0, o[dt][1] * i0);
        g_ah[row2 + w] = pack_h2(o[dt][2] * i1, o[dt][3] * i1);
    }
}

// ---------------- launcher ---------------------------------------------------
extern "C" void kernel_launch(void* const* d_in, const int* in_sizes, int n_in,
                              void* d_out, int out_size)
{
    const float* x_q = (const float*)d_in[0];
    const float* x_k = (const float*)d_in[1];
    const float* x_v = (const float*)d_in[2];
    const float* w_q = (const float*)d_in[3];
    const float* w_k = (const float*)d_in[4];
    const float* w_v = (const float*)d_in[5];
    const float* w_o = (const float*)d_in[6];
    const int*   msk = (const int*)d_in[7];
    float* out = (float*)d_out;

    cudaFuncSetAttribute((const void*)proj_kernel,    cudaFuncAttributeMaxDynamicSharedMemorySize, GSM_BYTES);
    cudaFuncSetAttribute((const void*)outproj_kernel, cudaFuncAttributeMaxDynamicSharedMemorySize, GSM_BYTES);
    cudaFuncSetAttribute((const void*)flash_kernel,   cudaFuncAttributeMaxDynamicSharedMemorySize, FSM_BYTES);

    // one-time pre-split conversions
    conv_x_kernel<<<dim3(MROWS * 512 / 256, 1, 3), 256>>>(x_q, x_k, x_v);
    conv_w_kernel<<<dim3(512 * 1024 / 256, 4), 256>>>(w_q, w_k, w_v, w_o);

    // fused Q/K/V projections (Q,K: x3; V: x1)
    proj_kernel<<<dim3(MROWS / 128, NHEAD / 2, 3), 256, GSM_BYTES>>>();

    flash_kernel<<<dim3(SEQL / 128, BH), 256, FSM_BYTES>>>(msk);

    // output projection: x1
    outproj_kernel<<<dim3(MROWS / 128, EMB / 128, 1), 256, GSM_BYTES>>>(out);
}

// round 17
// speedup vs baseline: 1.1994x; 1.0353x over previous
#include <cuda_runtime.h>
#include <cuda_fp16.h>
#include <cstdint>

#define BATCHN 4
#define SEQL   2048
#define EMB    1024
#define NHEAD  16
#define DKH    64
#define MROWS  (BATCHN*SEQL)   /* 8192 */
#define BH     (BATCHN*NHEAD)  /* 64 */

// ---------------- scratch (static device globals; no runtime allocation) ----
__device__ unsigned g_xh[3][(size_t)MROWS*512];   // x hi, [row][kpair]
__device__ unsigned g_xl[3][(size_t)MROWS*512];   // lo
__device__ unsigned g_wh[4][(size_t)1024*512];    // weights hi, [col][kpair]  (BT layout)
__device__ unsigned g_wl[2][(size_t)1024*512];    // weights lo (Q,K only)
__device__ unsigned g_qh[(size_t)BH*SEQL*32];     // q hi (scaled by 8*log2e)
__device__ unsigned g_ql[(size_t)BH*SEQL*32];
__device__ unsigned g_kh[(size_t)BH*SEQL*32];
__device__ unsigned g_kl[(size_t)BH*SEQL*32];
__device__ unsigned g_vh[(size_t)BH*SEQL*32];     // v hi only
__device__ unsigned g_ah[(size_t)MROWS*512];      // attn out hi, [row][epair]

#define LOG2E 1.4426950408889634f

// ---------------- helpers ---------------------------------------------------
__device__ __forceinline__ void mma16h(float c[4], unsigned a0, unsigned a1, unsigned a2, unsigned a3,
                                       unsigned b0, unsigned b1) {
    asm volatile(
        "mma.sync.aligned.m16n8k16.row.col.f32.f16.f16.f32 "
        "{%0,%1,%2,%3},{%4,%5,%6,%7},{%8,%9},{%0,%1,%2,%3};\n"
        : "+f"(c[0]), "+f"(c[1]), "+f"(c[2]), "+f"(c[3])
        : "r"(a0), "r"(a1), "r"(a2), "r"(a3), "r"(b0), "r"(b1));
}
__device__ __forceinline__ void ldm4(uint4 &r, uint32_t a) {
    asm volatile("ldmatrix.sync.aligned.m8n8.x4.shared.b16 {%0,%1,%2,%3}, [%4];"
                 : "=r"(r.x), "=r"(r.y), "=r"(r.z), "=r"(r.w) : "r"(a));
}
__device__ __forceinline__ void split_h2(float x0, float x1, unsigned &hi, unsigned &lo) {
    __half2 H = __floats2half2_rn(x0, x1);
    float2 f = __half22float2(H);
    __half2 L = __floats2half2_rn(x0 - f.x, x1 - f.y);
    hi = *reinterpret_cast<unsigned*>(&H);
    lo = *reinterpret_cast<unsigned*>(&L);
}
__device__ __forceinline__ unsigned pack_h2(float x0, float x1) {
    __half2 H = __floats2half2_rn(x0, x1);
    return *reinterpret_cast<unsigned*>(&H);
}
__device__ __forceinline__ uint32_t smem_u32(const void* p) {
    uint32_t a;
    asm("{ .reg .u64 t; cvta.to.shared.u64 t, %1; cvt.u32.u64 %0, t; }" : "=r"(a) : "l"(p));
    return a;
}
#define CPA16(dst, src) asm volatile("cp.async.cg.shared.global [%0], [%1], 16;" :: "r"(dst), "l"(src))
#define CPA_COMMIT()    asm volatile("cp.async.commit_group;" ::: "memory")
#define CPA_WAIT0()     asm volatile("cp.async.wait_group 0;" ::: "memory")

// ---------------- conversion kernels -----------------------------------------
__global__ void __launch_bounds__(256) conv_x_kernel(
    const float* __restrict__ x0, const float* __restrict__ x1, const float* __restrict__ x2)
{
    int sel = blockIdx.z;
    const float* x = sel == 0 ? x0 : (sel == 1 ? x1 : x2);
    size_t idx = (size_t)blockIdx.x * 256 + threadIdx.x;
    float2 v = *reinterpret_cast<const float2*>(x + 2 * idx);
    unsigned h, l;
    split_h2(v.x, v.y, h, l);
    g_xh[sel][idx] = h;
    g_xl[sel][idx] = l;
}

__global__ void __launch_bounds__(256) conv_w_kernel(
    const float* __restrict__ w0, const float* __restrict__ w1,
    const float* __restrict__ w2, const float* __restrict__ w3)
{
    int wsel = blockIdx.y;
    const float* W = wsel == 0 ? w0 : (wsel == 1 ? w1 : (wsel == 2 ? w2 : w3));
    size_t idx = (size_t)blockIdx.x * 256 + threadIdx.x;
    int p   = (int)(idx >> 10);
    int col = (int)(idx & 1023);
    float v0, v1;
    if (wsel < 3) {
        int head = col >> 6, d = col & 63;
        size_t base = (size_t)head * EMB * 64 + (size_t)(2 * p) * 64 + d;
        v0 = W[base];
        v1 = W[base + 64];
    } else {
        v0 = W[(size_t)(2 * p) * EMB + col];
        v1 = W[(size_t)(2 * p + 1) * EMB + col];
    }
    unsigned h, l;
    split_h2(v0, v1, h, l);
    g_wh[wsel][(size_t)col * 512 + p] = h;
    if (wsel < 2) g_wl[wsel][(size_t)col * 512 + p] = l;
}

// ---------------- GEMM body (pre-split fp16, ldmatrix fragments) -------------
#define TW 20
#define CHUNK 32
#define GSTAGE (4*128*TW)
#define GSM_BYTES (2 * GSTAGE * 4)   /* 81920 */

template<int MODE, int PASSES>
__device__ __forceinline__ void gemm_body(unsigned* smu, float* __restrict__ Cext, int sel)
{
    constexpr int G_AH = 0;
    constexpr int G_AL = 128 * TW;
    constexpr int G_BH = 2 * 128 * TW;
    constexpr int G_BL = 3 * 128 * TW;
    constexpr int NCH = EMB / CHUNK;   // 32
    constexpr int BKP = CHUNK / 2;     // 16

    const uint32_t sbase = smem_u32(smu);

    const int tid  = threadIdx.x;
    const int lane = tid & 31;
    const int warp = tid >> 5;
    const int wm = warp >> 1, wn = warp & 1;
    const int row0 = blockIdx.x * 128;
    const int col0 = blockIdx.y * 128;

    const unsigned* Ahg = (MODE == 0) ? g_xh[sel] : g_ah;
    const unsigned* Alg = (MODE == 0) ? g_xl[sel] : g_ah;
    const unsigned* Whg = g_wh[sel];
    const unsigned* Wlg = g_wl[sel < 2 ? sel : 0];

    float acc[2][8][4];
#pragma unroll
    for (int i = 0; i < 2; i++)
#pragma unroll
        for (int j = 0; j < 8; j++)
#pragma unroll
            for (int r = 0; r < 4; r++) acc[i][j][r] = 0.f;

    const int am = tid & 127;
    const int ps = tid >> 7;

    const int a_off = (wm * 32 + (lane & 15)) * TW + (lane >> 4) * 4;
    const int b_off = (wn * 64 + ((lane >> 4) << 3) + (lane & 7)) * TW + ((lane >> 3) & 1) * 4;

    auto issue = [&](int c, int st) {
        {
            const unsigned* srcH = Ahg + (size_t)(row0 + am) * 512 + c * BKP + ps * 8;
            uint32_t dH = sbase + (uint32_t)(st * GSTAGE + G_AH + am * TW + ps * 8) * 4;
            CPA16(dH, srcH); CPA16(dH + 16, srcH + 4);
            if (PASSES >= 2) {
                const unsigned* srcL = Alg + (size_t)(row0 + am) * 512 + c * BKP + ps * 8;
                uint32_t dL = sbase + (uint32_t)(st * GSTAGE + G_AL + am * TW + ps * 8) * 4;
                CPA16(dL, srcL); CPA16(dL + 16, srcL + 4);
            }
        }
        {
#pragma unroll
            for (int a = 0; a < 2; a++) {
                int seg = tid + a * 256;
                int cl = seg >> 2, pt = (seg & 3) * 4;
                const unsigned* srcH = Whg + (size_t)(col0 + cl) * 512 + c * BKP + pt;
                uint32_t dH = sbase + (uint32_t)(st * GSTAGE + G_BH + cl * TW + pt) * 4;
                CPA16(dH, srcH);
                if (PASSES >= 3) {
                    const unsigned* srcL = Wlg + (size_t)(col0 + cl) * 512 + c * BKP + pt;
                    uint32_t dL = sbase + (uint32_t)(st * GSTAGE + G_BL + cl * TW + pt) * 4;
                    CPA16(dL, srcL);
                }
            }
        }
        CPA_COMMIT();
    };

    issue(0, 0);

    for (int c = 0; c < NCH; c++) {
        const int st = c & 1;
        CPA_WAIT0();
        __syncthreads();
        if (c + 1 < NCH) issue(c + 1, st ^ 1);

        const uint32_t stb = sbase + (uint32_t)(st * GSTAGE) * 4;

#pragma unroll
        for (int ks = 0; ks < 2; ks++) {
            const int kw = ks * 8;
            uint4 ah[2], al[2];
#pragma unroll
            for (int mt = 0; mt < 2; mt++) {
                uint32_t aw = stb + (uint32_t)(a_off + mt * 16 * TW + kw) * 4;
                ldm4(ah[mt], aw + G_AH * 4);
                if (PASSES >= 2) ldm4(al[mt], aw + G_AL * 4);
            }
#pragma unroll
            for (int ntp = 0; ntp < 4; ntp++) {
                uint32_t bw = stb + (uint32_t)(b_off + ntp * 16 * TW + kw) * 4;
                uint4 bh; ldm4(bh, bw + G_BH * 4);
#pragma unroll
                for (int mt = 0; mt < 2; mt++) {
                    mma16h(acc[mt][2*ntp],   ah[mt].x, ah[mt].y, ah[mt].z, ah[mt].w, bh.x, bh.y);
                    mma16h(acc[mt][2*ntp+1], ah[mt].x, ah[mt].y, ah[mt].z, ah[mt].w, bh.z, bh.w);
                    if (PASSES >= 2) {
                        mma16h(acc[mt][2*ntp],   al[mt].x, al[mt].y, al[mt].z, al[mt].w, bh.x, bh.y);
                        mma16h(acc[mt][2*ntp+1], al[mt].x, al[mt].y, al[mt].z, al[mt].w, bh.z, bh.w);
                    }
                }
                if (PASSES >= 3) {
                    uint4 bl; ldm4(bl, bw + G_BL * 4);
#pragma unroll
                    for (int mt = 0; mt < 2; mt++) {
                        mma16h(acc[mt][2*ntp],   ah[mt].x, ah[mt].y, ah[mt].z, ah[mt].w, bl.x, bl.y);
                        mma16h(acc[mt][2*ntp+1], ah[mt].x, ah[mt].y, ah[mt].z, ah[mt].w, bl.z, bl.w);
                    }
                }
            }
        }
        __syncthreads();
    }

    // ---- epilogue ----
    const float qscale = 8.f * LOG2E;
    const int r8 = lane >> 2, lq = lane & 3;
#pragma unroll
    for (int mt = 0; mt < 2; mt++) {
        int r = row0 + wm * 32 + mt * 16 + r8;
#pragma unroll
        for (int nt = 0; nt < 8; nt++) {
            int cc = wn * 64 + nt * 8 + lq * 2;
            if (MODE == 0) {
                int b = r >> 11, s = r & 2047;
                int head = blockIdx.y * 2 + (cc >> 6);
                int w = (cc & 63) >> 1;
                size_t widx  = ((size_t)(b * NHEAD + head) * SEQL + s) * 32 + w;
                size_t widx2 = widx + (size_t)8 * 32;
                float v0 = acc[mt][nt][0], v1 = acc[mt][nt][1];
                float v2 = acc[mt][nt][2], v3 = acc[mt][nt][3];
                if (sel == 0) { v0 *= qscale; v1 *= qscale; v2 *= qscale; v3 *= qscale; }
                unsigned h0, l0, h1, l1;
                split_h2(v0, v1, h0, l0);
                split_h2(v2, v3, h1, l1);
                if (sel == 0) {
                    g_qh[widx] = h0;  g_ql[widx] = l0;
                    g_qh[widx2] = h1; g_ql[widx2] = l1;
                } else if (sel == 1) {
                    g_kh[widx] = h0;  g_kl[widx] = l0;
                    g_kh[widx2] = h1; g_kl[widx2] = l1;
                } else {
                    g_vh[widx] = h0;
                    g_vh[widx2] = h1;
                }
            } else {
                size_t base = (size_t)r * EMB + col0 + cc;
                Cext[base]               = acc[mt][nt][0];
                Cext[base + 1]           = acc[mt][nt][1];
                Cext[base + 8 * EMB]     = acc[mt][nt][2];
                Cext[base + 8 * EMB + 1] = acc[mt][nt][3];
            }
        }
    }
}

__global__ void __launch_bounds__(256, 2) proj_kernel()
{
    extern __shared__ unsigned smu[];
    int sel = blockIdx.z;
    if (sel < 2) gemm_body<0, 3>(smu, nullptr, sel);
    else         gemm_body<0, 1>(smu, nullptr, 2);
}

__global__ void __launch_bounds__(256, 2) outproj_kernel(float* __restrict__ Cext)
{
    extern __shared__ unsigned smu[];
    gemm_body<1, 1>(smu, Cext, 3);
}

// ---------------- flash attention (causal), pre-split fp16, 2 CTAs/SM --------
#define QW 36
#define KW 36
#define PW 68
#define FQ_H 0
#define FQ_L (128*QW)
#define FK_H 0
#define FK_L (64*KW)
#define FV_H (2*64*KW)
#define FSM_WORDS (2*128*QW)
#define FSM_BYTES (FSM_WORDS*4)

__global__ void __launch_bounds__(256, 2) flash_kernel(const int* __restrict__ maskp)
{
    extern __shared__ unsigned smw[];

    const int tid  = threadIdx.x;
    const int lane = tid & 31;
    const int warp = tid >> 5;
    const int r8 = lane >> 2, lq = lane & 3;
    const int qt = gridDim.x - 1 - blockIdx.x;   // heavy CTAs first
    const int bh = blockIdx.y;
    const int b = bh >> 4, h = bh & 15;
    const int q0 = qt * 128;
    const size_t sb = (size_t)bh * SEQL;

#pragma unroll
    for (int ii = 0; ii < 4; ii++) {
        int i = tid + ii * 256;
        int r = i >> 3, sg = (i & 7) * 4;
        uint4 vh = *reinterpret_cast<const uint4*>(g_qh + (sb + q0 + r) * 32 + sg);
        uint4 vl = *reinterpret_cast<const uint4*>(g_ql + (sb + q0 + r) * 32 + sg);
        *reinterpret_cast<uint4*>(smw + FQ_H + r * QW + sg) = vh;
        *reinterpret_cast<uint4*>(smw + FQ_L + r * QW + sg) = vl;
    }
    __syncthreads();

    const int rl = warp * 16 + r8;
    unsigned qh[4][4], ql[4][4];
#pragma unroll
    for (int ks = 0; ks < 4; ks++) {
        int base = rl * QW + ks * 8 + lq;
        qh[ks][0] = smw[FQ_H + base];
        qh[ks][1] = smw[FQ_H + base + 8 * QW];
        qh[ks][2] = smw[FQ_H + base + 4];
        qh[ks][3] = smw[FQ_H + base + 8 * QW + 4];
        ql[ks][0] = smw[FQ_L + base];
        ql[ks][1] = smw[FQ_L + base + 8 * QW];
        ql[ks][2] = smw[FQ_L + base + 4];
        ql[ks][3] = smw[FQ_L + base + 8 * QW + 4];
    }
    __syncthreads();

    float m[2] = { -1e30f, -1e30f };
    float l[2] = { 0.f, 0.f };
    float o[8][4];
#pragma unroll
    for (int i = 0; i < 8; i++)
#pragma unroll
        for (int j = 0; j < 4; j++) o[i][j] = 0.f;

    const int maskv = maskp[0];
    const int tdiag = 2 * qt + (warp >> 2);
    const int ntiles = maskv ? (2 * qt + 2) : (SEQL / 64);

    __half* vhp = reinterpret_cast<__half*>(smw + FV_H);

    for (int t = 0; t < ntiles; t++) {
        const int kv0 = t * 64;

        if (t > 0) __syncthreads();
#pragma unroll
        for (int ii = 0; ii < 2; ii++) {
            int i = tid + ii * 256;
            int r = i >> 3, sg = (i & 7) * 4;
            uint4 vh = *reinterpret_cast<const uint4*>(g_kh + (sb + kv0 + r) * 32 + sg);
            uint4 vl = *reinterpret_cast<const uint4*>(g_kl + (sb + kv0 + r) * 32 + sg);
            *reinterpret_cast<uint4*>(smw + FK_H + r * KW + sg) = vh;
            *reinterpret_cast<uint4*>(smw + FK_L + r * KW + sg) = vl;
        }
#pragma unroll
        for (int ii = 0; ii < 4; ii++) {
            int i = tid + ii * 256;
            int r = i >> 4, c4 = (i & 15) << 2;
            uint2 w2 = *reinterpret_cast<const uint2*>(g_vh + (sb + kv0 + r) * 32 + (c4 >> 1));
            __half2 p0 = *reinterpret_cast<__half2*>(&w2.x);
            __half2 p1 = *reinterpret_cast<__half2*>(&w2.y);
            int p = r >> 1, rb = r & 1;
            vhp[(p * PW + c4 + 0) * 2 + rb] = __low2half(p0);
            vhp[(p * PW + c4 + 1) * 2 + rb] = __high2half(p0);
            vhp[(p * PW + c4 + 2) * 2 + rb] = __low2half(p1);
            vhp[(p * PW + c4 + 3) * 2 + rb] = __high2half(p1);
        }
        __syncthreads();

        if (maskv && t > tdiag) continue;

        float s[8][4];
#pragma unroll
        for (int i = 0; i < 8; i++)
#pragma unroll
            for (int j = 0; j < 4; j++) s[i][j] = 0.f;

        const int ntmax = (maskv && t == tdiag) ? (2 * (warp & 3) + 2) : 8;
#pragma unroll
        for (int ks = 0; ks < 4; ks++) {
#pragma unroll
            for (int nt = 0; nt < 8; nt++) {
                if (nt >= ntmax) break;
                int n = nt * 8 + r8;
                unsigned bh0 = smw[FK_H + n * KW + ks * 8 + lq];
                unsigned bh1 = smw[FK_H + n * KW + ks * 8 + lq + 4];
                unsigned bl0 = smw[FK_L + n * KW + ks * 8 + lq];
                unsigned bl1 = smw[FK_L + n * KW + ks * 8 + lq + 4];
                mma16h(s[nt], qh[ks][0], qh[ks][1], qh[ks][2], qh[ks][3], bh0, bh1);
                mma16h(s[nt], qh[ks][0], qh[ks][1], qh[ks][2], qh[ks][3], bl0, bl1);
                mma16h(s[nt], ql[ks][0], ql[ks][1], ql[ks][2], ql[ks][3], bh0, bh1);
            }
        }

        if (maskv && t == tdiag) {
            int rg0 = q0 + rl;
#pragma unroll
            for (int nt = 0; nt < 8; nt++) {
                int cg = kv0 + nt * 8 + lq * 2;
                if (cg > rg0)         s[nt][0] = -1e30f;
                if (cg + 1 > rg0)     s[nt][1] = -1e30f;
                if (cg > rg0 + 8)     s[nt][2] = -1e30f;
                if (cg + 1 > rg0 + 8) s[nt][3] = -1e30f;
            }
        }

#pragma unroll
        for (int sub = 0; sub < 2; sub++) {
            float tm = -1e30f;
#pragma unroll
            for (int nt = 0; nt < 8; nt++)
                tm = fmaxf(tm, fmaxf(s[nt][2 * sub], s[nt][2 * sub + 1]));
            tm = fmaxf(tm, __shfl_xor_sync(0xffffffffu, tm, 1));
            tm = fmaxf(tm, __shfl_xor_sync(0xffffffffu, tm, 2));
            float mn = fmaxf(m[sub], tm);
            float alpha = exp2f(m[sub] - mn);
            float rs = 0.f;
#pragma unroll
            for (int nt = 0; nt < 8; nt++) {
                float p0 = exp2f(s[nt][2 * sub] - mn);
                float p1 = exp2f(s[nt][2 * sub + 1] - mn);
                s[nt][2 * sub] = p0; s[nt][2 * sub + 1] = p1;
                rs += p0 + p1;
            }
            rs += __shfl_xor_sync(0xffffffffu, rs, 1);
            rs += __shfl_xor_sync(0xffffffffu, rs, 2);
            l[sub] = l[sub] * alpha + rs;
            m[sub] = mn;
#pragma unroll
            for (int dt = 0; dt < 8; dt++) {
                o[dt][2 * sub]     *= alpha;
                o[dt][2 * sub + 1] *= alpha;
            }
        }

        unsigned pa[4][4];
#pragma unroll
        for (int ks = 0; ks < 4; ks++) {
            pa[ks][0] = pack_h2(s[2*ks][0],   s[2*ks][1]);
            pa[ks][1] = pack_h2(s[2*ks][2],   s[2*ks][3]);
            pa[ks][2] = pack_h2(s[2*ks+1][0], s[2*ks+1][1]);
            pa[ks][3] = pack_h2(s[2*ks+1][2], s[2*ks+1][3]);
        }

        int ksmax = (maskv && t == tdiag) ? ((warp & 3) + 1) : 4;
#pragma unroll
        for (int ks = 0; ks < 4; ks++) {
            if (ks >= ksmax) break;
#pragma unroll
            for (int dt = 0; dt < 8; dt++) {
                int d = dt * 8 + r8;
                unsigned bh0 = smw[FV_H + (ks * 8 + lq) * PW + d];
                unsigned bh1 = smw[FV_H + (ks * 8 + lq + 4) * PW + d];
                mma16h(o[dt], pa[ks][0], pa[ks][1], pa[ks][2], pa[ks][3], bh0, bh1);
            }
        }
    }

    // ---- epilogue: attn output hi-only (out-proj is x1) ----
    float i0 = 1.f / l[0];
    float i1 = 1.f / l[1];
    int rg = q0 + rl;
    size_t row  = (size_t)(b * SEQL + rg) * 512;
    size_t row2 = row + (size_t)8 * 512;
#pragma unroll
    for (int dt = 0; dt < 8; dt++) {
        int w = h * 32 + dt * 4 + lq;
        g_ah[row + w]  = pack_h2(o[dt][0] * i0, o[dt][1] * i0);
        g_ah[row2 + w] = pack_h2(o[dt][2] * i1, o[dt][3] * i1);
    }
}

// ---------------- launcher ---------------------------------------------------
extern "C" void kernel_launch(void* const* d_in, const int* in_sizes, int n_in,
                              void* d_out, int out_size)
{
    const float* x_q = (const float*)d_in[0];
    const float* x_k = (const float*)d_in[1];
    const float* x_v = (const float*)d_in[2];
    const float* w_q = (const float*)d_in[3];
    const float* w_k = (const float*)d_in[4];
    const float* w_v = (const float*)d_in[5];
    const float* w_o = (const float*)d_in[6];
    const int*   msk = (const int*)d_in[7];
    float* out = (float*)d_out;

    cudaFuncSetAttribute((const void*)proj_kernel,    cudaFuncAttributeMaxDynamicSharedMemorySize, GSM_BYTES);
    cudaFuncSetAttribute((const void*)outproj_kernel, cudaFuncAttributeMaxDynamicSharedMemorySize, GSM_BYTES);
    cudaFuncSetAttribute((const void*)flash_kernel,   cudaFuncAttributeMaxDynamicSharedMemorySize, FSM_BYTES);

    // one-time pre-split conversions
    conv_x_kernel<<<dim3(MROWS * 512 / 256, 1, 3), 256>>>(x_q, x_k, x_v);
    conv_w_kernel<<<dim3(512 * 1024 / 256, 4), 256>>>(w_q, w_k, w_v, w_o);

    // fused Q/K/V projections (Q,K: x3; V: x1)
    proj_kernel<<<dim3(MROWS / 128, NHEAD / 2, 3), 256, GSM_BYTES>>>();

    flash_kernel<<<dim3(SEQL / 128, BH), 256, FSM_BYTES>>>(msk);

    // output projection: x1
    outproj_kernel<<<dim3(MROWS / 128, EMB / 128, 1), 256, GSM_BYTES>>>(out);
}